// round 9
// baseline (speedup 1.0000x reference)
#include <cuda_runtime.h>
#include <cuda_fp16.h>
#include <cstdint>
#include <math_constants.h>

// Mahalanobis max-score, pipelined HMMA.
// Per 16-row tile (one warp): D[16, 88] = A @ B via mma.m16n8k16:
//   nt 0..7  (cols 0..63):  D = Fhi @ P        (fp16 P, hi-only; qf uses fh+2fl trick)
//   nt 8..10 (cols 64..87): D = (Fhi+Flo) @ (muP hi/lo col pairs)  -- exact cross
// Loads: LDG.128 -> split fp16 hi/lo -> swizzled warp-private smem -> ldmatrix.
// Software-pipelined at half-tile (k 0..31 / 32..63) granularity.
// out[m] = alpha * (max_c (Dh+Dl - 0.5 qmu_c) - 0.5 * sum_k (fh+2fl)[k] D[m,k])

#define DD 64
#define CC 10

static __device__ __forceinline__ uint32_t smem_u32(const void* p) {
    uint32_t a;
    asm("{ .reg .u64 t; cvta.to.shared.u64 t, %1; cvt.u32.u64 %0, t; }" : "=r"(a) : "l"(p));
    return a;
}
static __device__ __forceinline__ void ldsm4(uint32_t* r, uint32_t addr) {
    asm volatile("ldmatrix.sync.aligned.m8n8.x4.shared.b16 {%0,%1,%2,%3}, [%4];"
                 : "=r"(r[0]), "=r"(r[1]), "=r"(r[2]), "=r"(r[3]) : "r"(addr));
}
static __device__ __forceinline__ void mma16816(float* d, const uint32_t* a, const uint32_t* b) {
    asm volatile(
        "mma.sync.aligned.m16n8k16.row.col.f32.f16.f16.f32 "
        "{%0,%1,%2,%3}, {%4,%5,%6,%7}, {%8,%9}, {%0,%1,%2,%3};"
        : "+f"(d[0]), "+f"(d[1]), "+f"(d[2]), "+f"(d[3])
        : "r"(a[0]), "r"(a[1]), "r"(a[2]), "r"(a[3]), "r"(b[0]), "r"(b[1]));
}
static __device__ __forceinline__ uint32_t pack_h2(__half a, __half b) {
    union { __half2 h; uint32_t u; } cv; cv.h = __halves2half2(a, b); return cv.u;
}
static __device__ __forceinline__ float2 h2f(uint32_t u) {
    union { uint32_t u; __half2 h; } cv; cv.u = u; return __half22float2(cv.h);
}
static __device__ __forceinline__ __half muphalf(float v, bool lo) {
    __half h = __float2half_rn(v);
    return lo ? __float2half_rn(v - __half2float(h)) : h;
}
// swizzle for 128B rows: 16B-chunk index XOR (row & 7)
static __device__ __forceinline__ uint32_t swz(uint32_t row, uint32_t chunk) {
    return row * 128u + ((chunk ^ (row & 7u)) << 4);
}

__global__ __launch_bounds__(128, 2)
void mahal_pipe(const float* __restrict__ F, const float* __restrict__ mu,
                const float* __restrict__ P, const float* __restrict__ alpha_p,
                float* __restrict__ out, int nTiles16) {
    __shared__ float sMuP[CC * DD];
    __shared__ float sNegQ[16];
    __shared__ __align__(16) uint8_t sStage[4][4096];   // per warp: hi[2KB] | lo[2KB]

    const int tid = threadIdx.x;

    // ---- one-time prep: muP (fp32), -0.5*qmu ----
    for (int idx = tid; idx < CC * DD; idx += 128) {
        int c = idx >> 6, k = idx & 63;
        const float* mc = mu + c * DD;
        const float* pk = P + k * DD;        // P symmetric
        float s = 0.f;
        #pragma unroll 16
        for (int j = 0; j < DD; j++) s = fmaf(mc[j], pk[j], s);
        sMuP[idx] = s;
    }
    __syncthreads();
    if (tid < 16) {
        float v = 0.f;
        if (tid < CC) {
            float qq = 0.f;
            #pragma unroll 16
            for (int k = 0; k < DD; k++) qq = fmaf(sMuP[tid * DD + k], mu[tid * DD + k], qq);
            v = -0.5f * qq;
        }
        sNegQ[tid] = v;
    }
    __syncthreads();

    const int w  = tid >> 5;
    const int l  = tid & 31;
    const int q  = l & 3;
    const int tq = l >> 2;
    uint8_t* stage = sStage[w];
    const uint32_t uHi = smem_u32(stage);
    const uint32_t uLo = uHi + 2048;

    // ---- persistent B fragments in registers (verified R6 layout) ----
    uint32_t Bf[4][11][2];
    #pragma unroll
    for (int kk = 0; kk < 4; kk++) {
        #pragma unroll
        for (int nt = 0; nt < 11; nt++) {
            int n = 8 * nt + tq;
            int k0 = 16 * kk + 2 * q;
            uint32_t b0, b1;
            if (n < DD) {
                b0 = pack_h2(__float2half_rn(P[(k0    ) * DD + n]),
                             __float2half_rn(P[(k0 + 1) * DD + n]));
                b1 = pack_h2(__float2half_rn(P[(k0 + 8) * DD + n]),
                             __float2half_rn(P[(k0 + 9) * DD + n]));
            } else if (n < DD + 2 * CC) {
                int c = (n - DD) >> 1;
                bool lo = (n - DD) & 1;
                const float* mp = sMuP + c * DD;
                b0 = pack_h2(muphalf(mp[k0], lo),     muphalf(mp[k0 + 1], lo));
                b1 = pack_h2(muphalf(mp[k0 + 8], lo), muphalf(mp[k0 + 9], lo));
            } else { b0 = 0u; b1 = 0u; }
            Bf[kk][nt][0] = b0;
            Bf[kk][nt][1] = b1;
        }
    }

    const float alpha0 = __ldg(alpha_p);
    const float nq0 = sNegQ[q];
    const float nq1 = sNegQ[4 + q];
    const float nq2 = (q < 2) ? sNegQ[8 + q] : -CUDART_INF_F;

    // ldmatrix source addresses (R4-verified): lane -> row l&15, chunk 2kk + (l>>4)
    uint32_t offK[4];
    {
        uint32_t rl = (uint32_t)(l & 15), sel = (uint32_t)(l >> 4);
        #pragma unroll
        for (int kk = 0; kk < 4; kk++) offK[kk] = swz(rl, 2u * kk + sel);
    }
    // raw-load lane coords: per instr 8 rows x 64B contiguous
    const int lr = l & 7;
    const int lp = l >> 3;

    const int gw = blockIdx.x * 4 + w;
    const int stride = gridDim.x * 4;

    float4 rawA[4], rawB[4];

    // prologue: first tile half0 (tile = 16 rows x 64 f32 = 256 float4)
    if (gw < nTiles16) {
        const float4* b4 = reinterpret_cast<const float4*>(F) + (size_t)gw * 256;
        #pragma unroll
        for (int j = 0; j < 4; j++)
            rawA[j] = b4[(lr + 8 * (j >> 1)) * 16 + 4 * (j & 1) + lp];
    }

    for (int tile = gw; tile < nTiles16; tile += stride) {
        const float4* b4 = reinterpret_cast<const float4*>(F) + (size_t)tile * 256;
        // issue half1 loads
        #pragma unroll
        for (int j = 0; j < 4; j++)
            rawB[j] = b4[(lr + 8 * (j >> 1)) * 16 + 8 + 4 * (j & 1) + lp];

        // convert + stage half0 (c4 = 4*(j&1) + lp)
        #pragma unroll
        for (int j = 0; j < 4; j++) {
            int row = lr + 8 * (j >> 1);
            int c4 = 4 * (j & 1) + lp;
            uint32_t off = swz((uint32_t)row, (uint32_t)(c4 >> 1)) + (uint32_t)(c4 & 1) * 8;
            float4 v = rawA[j];
            __half hx = __float2half_rn(v.x), hy = __float2half_rn(v.y);
            __half hz = __float2half_rn(v.z), hw = __float2half_rn(v.w);
            __half lx = __float2half_rn(v.x - __half2float(hx));
            __half ly = __float2half_rn(v.y - __half2float(hy));
            __half lz = __float2half_rn(v.z - __half2float(hz));
            __half lw = __float2half_rn(v.w - __half2float(hw));
            uint2 H; H.x = pack_h2(hx, hy); H.y = pack_h2(hz, hw);
            uint2 L; L.x = pack_h2(lx, ly); L.y = pack_h2(lz, lw);
            *reinterpret_cast<uint2*>(stage + off) = H;
            *reinterpret_cast<uint2*>(stage + 2048 + off) = L;
        }
        __syncwarp();

        uint32_t Ah[4][4], Al[4][4];
        ldsm4(Ah[0], uHi + offK[0]);
        ldsm4(Al[0], uLo + offK[0]);
        ldsm4(Ah[1], uHi + offK[1]);
        ldsm4(Al[1], uLo + offK[1]);

        // prefetch next tile half0 (hidden behind MMA phase 1)
        {
            int tn = tile + stride;
            if (tn >= nTiles16) tn = tile;
            const float4* bn = reinterpret_cast<const float4*>(F) + (size_t)tn * 256;
            #pragma unroll
            for (int j = 0; j < 4; j++)
                rawA[j] = bn[(lr + 8 * (j >> 1)) * 16 + 4 * (j & 1) + lp];
        }

        float acc[11][4];
        #pragma unroll
        for (int nt = 0; nt < 11; nt++) {
            acc[nt][0] = 0.f; acc[nt][1] = 0.f; acc[nt][2] = 0.f; acc[nt][3] = 0.f;
        }
        // MMA phase 1 (kk 0,1): hi all nt, lo cross only
        #pragma unroll
        for (int kk = 0; kk < 2; kk++) {
            #pragma unroll
            for (int nt = 0; nt < 11; nt++) mma16816(acc[nt], Ah[kk], Bf[kk][nt]);
            #pragma unroll
            for (int nt = 8; nt < 11; nt++) mma16816(acc[nt], Al[kk], Bf[kk][nt]);
        }

        // convert + stage half1 (c4 = 8 + 4*(j&1) + lp)
        #pragma unroll
        for (int j = 0; j < 4; j++) {
            int row = lr + 8 * (j >> 1);
            int c4 = 8 + 4 * (j & 1) + lp;
            uint32_t off = swz((uint32_t)row, (uint32_t)(c4 >> 1)) + (uint32_t)(c4 & 1) * 8;
            float4 v = rawB[j];
            __half hx = __float2half_rn(v.x), hy = __float2half_rn(v.y);
            __half hz = __float2half_rn(v.z), hw = __float2half_rn(v.w);
            __half lx = __float2half_rn(v.x - __half2float(hx));
            __half ly = __float2half_rn(v.y - __half2float(hy));
            __half lz = __float2half_rn(v.z - __half2float(hz));
            __half lw = __float2half_rn(v.w - __half2float(hw));
            uint2 H; H.x = pack_h2(hx, hy); H.y = pack_h2(hz, hw);
            uint2 L; L.x = pack_h2(lx, ly); L.y = pack_h2(lz, lw);
            *reinterpret_cast<uint2*>(stage + off) = H;
            *reinterpret_cast<uint2*>(stage + 2048 + off) = L;
        }
        __syncwarp();

        ldsm4(Ah[2], uHi + offK[2]);
        ldsm4(Al[2], uLo + offK[2]);
        ldsm4(Ah[3], uHi + offK[3]);
        ldsm4(Al[3], uLo + offK[3]);

        // MMA phase 2 (kk 2,3)
        #pragma unroll
        for (int kk = 2; kk < 4; kk++) {
            #pragma unroll
            for (int nt = 0; nt < 11; nt++) mma16816(acc[nt], Ah[kk], Bf[kk][nt]);
            #pragma unroll
            for (int nt = 8; nt < 11; nt++) mma16816(acc[nt], Al[kk], Bf[kk][nt]);
        }

        // ---- epilogue: qf = sum_k (fh + 2 fl)[k] * D[m,k] ----
        float qf0 = 0.f, qf1 = 0.f;
        #pragma unroll
        for (int nt = 0; nt < 8; nt++) {
            int kk = nt >> 1;
            int i0 = (nt & 1) ? 2 : 0;
            float2 h0 = h2f(Ah[kk][i0]),     l0 = h2f(Al[kk][i0]);
            float2 h1 = h2f(Ah[kk][i0 + 1]), l1 = h2f(Al[kk][i0 + 1]);
            qf0 = fmaf(fmaf(2.f, l0.x, h0.x), acc[nt][0], qf0);
            qf0 = fmaf(fmaf(2.f, l0.y, h0.y), acc[nt][1], qf0);
            qf1 = fmaf(fmaf(2.f, l1.x, h1.x), acc[nt][2], qf1);
            qf1 = fmaf(fmaf(2.f, l1.y, h1.y), acc[nt][3], qf1);
        }
        // class scores: thread q holds class q (nt8), 4+q (nt9), 8+q (nt10, q<2)
        float s0 = acc[8][0] + acc[8][1] + nq0;
        float s1 = acc[8][2] + acc[8][3] + nq0;
        s0 = fmaxf(s0, acc[9][0] + acc[9][1] + nq1);
        s1 = fmaxf(s1, acc[9][2] + acc[9][3] + nq1);
        s0 = fmaxf(s0, acc[10][0] + acc[10][1] + nq2);
        s1 = fmaxf(s1, acc[10][2] + acc[10][3] + nq2);

        #pragma unroll
        for (int o = 1; o <= 2; o <<= 1) {
            qf0 += __shfl_xor_sync(0xffffffffu, qf0, o);
            qf1 += __shfl_xor_sync(0xffffffffu, qf1, o);
            s0 = fmaxf(s0, __shfl_xor_sync(0xffffffffu, s0, o));
            s1 = fmaxf(s1, __shfl_xor_sync(0xffffffffu, s1, o));
        }
        if (q == 0) {
            float* o = out + (size_t)tile * 16;
            o[tq]     = alpha0 * (s0 - 0.5f * qf0);
            o[tq + 8] = alpha0 * (s1 - 0.5f * qf1);
        }
    }
}

extern "C" void kernel_launch(void* const* d_in, const int* in_sizes, int n_in,
                              void* d_out, int out_size) {
    const float* features = (const float*)d_in[0];
    const float* mu       = (const float*)d_in[1];
    const float* P        = (const float*)d_in[2];
    const float* alpha    = (const float*)d_in[3];
    float* out = (float*)d_out;

    int n = in_sizes[0] / DD;
    int nTiles16 = n / 16;

    mahal_pipe<<<296, 128>>>(features, mu, P, alpha, out, nTiles16);
}

// round 10
// speedup vs baseline: 1.5411x; 1.5411x over previous
#include <cuda_runtime.h>
#include <cuda_fp16.h>
#include <cstdint>
#include <math_constants.h>

// Mahalanobis max-score, all-register HMMA with permuted-k coalesced loads and
// one-tile-ahead register pipeline.
// Per 16-row tile (one warp): D[16, 88] = Fhi @ B via mma.m16n8k16 (44 MMAs):
//   logical B cols 0..63: P (fp16), with k-perm pi and n-perm sigma so that
//     a-frags are direct float4 loads and qf pairing stays thread-local.
//   cols 64..83: hi/lo fp16 col pairs of muP (cross = fh . muP, exact split)
// qf = sum_k (fh + 2 fl)[k] * D[m,k]  (fl P fl dropped, ~2^-22)
// out[m] = alpha * (max_c (Dh+Dl - 0.5 qmu_c) - 0.5 * qf)

#define DD 64
#define CC 10

static __device__ __forceinline__ void mma16816(float* d, const uint32_t* a, const uint32_t* b) {
    asm volatile(
        "mma.sync.aligned.m16n8k16.row.col.f32.f16.f16.f32 "
        "{%0,%1,%2,%3}, {%4,%5,%6,%7}, {%8,%9}, {%0,%1,%2,%3};"
        : "+f"(d[0]), "+f"(d[1]), "+f"(d[2]), "+f"(d[3])
        : "r"(a[0]), "r"(a[1]), "r"(a[2]), "r"(a[3]), "r"(b[0]), "r"(b[1]));
}
static __device__ __forceinline__ uint32_t pack_h2(__half a, __half b) {
    union { __half2 h; uint32_t u; } cv; cv.h = __halves2half2(a, b); return cv.u;
}
static __device__ __forceinline__ float2 h2f(uint32_t u) {
    union { uint32_t u; __half2 h; } cv; cv.u = u; return __half22float2(cv.h);
}
// split float pair -> packed fp16 hi and lo (hi+lo == v to ~2^-22 rel)
static __device__ __forceinline__ void split2(float x, float y, uint32_t& h, uint32_t& l) {
    __half2 hh = __float22half2_rn(make_float2(x, y));
    float2 hf = __half22float2(hh);
    __half2 ll = __float22half2_rn(make_float2(x - hf.x, y - hf.y));
    union { __half2 h; uint32_t u; } a, b;
    a.h = hh; b.h = ll;
    h = a.u; l = b.u;
}
static __device__ __forceinline__ __half muphalf(float v, bool lo) {
    __half h = __float2half_rn(v);
    return lo ? __float2half_rn(v - __half2float(h)) : h;
}

__global__ __launch_bounds__(128, 2)
void mahal_v10(const float* __restrict__ F, const float* __restrict__ mu,
               const float* __restrict__ P, const float* __restrict__ alpha_p,
               float* __restrict__ out, int nTiles16) {
    __shared__ float sMuP[CC * DD];
    __shared__ float sNegQ[16];

    const int tid = threadIdx.x;

    // ---- one-time prep: muP (fp32), -0.5*qmu ----
    for (int idx = tid; idx < CC * DD; idx += 128) {
        int c = idx >> 6, k = idx & 63;
        const float* mc = mu + c * DD;
        const float* pk = P + k * DD;        // P symmetric
        float s = 0.f;
        #pragma unroll 16
        for (int j = 0; j < DD; j++) s = fmaf(mc[j], pk[j], s);
        sMuP[idx] = s;
    }
    __syncthreads();
    if (tid < 16) {
        float v = 0.f;
        if (tid < CC) {
            float qq = 0.f;
            #pragma unroll 16
            for (int k = 0; k < DD; k++) qq = fmaf(sMuP[tid * DD + k], mu[tid * DD + k], qq);
            v = -0.5f * qq;
        }
        sNegQ[tid] = v;
    }
    __syncthreads();

    const int w  = tid >> 5;
    const int l  = tid & 31;
    const int q  = l & 3;
    const int tq = l >> 2;

    // ---- persistent B fragments, permuted layout ----
    // nt<8 (P block): b-frag col n' = 8nt+tq maps to physical P col
    //   pcol = 16*(nt>>1) + 4*(tq>>1) + 2*(nt&1) + (tq&1)    (sigma)
    //   k rows (physical, pi): b0 -> 16kk+4q, +1 ; b1 -> 16kk+4q+2, +3
    // nt>=8 (cross): cols unpermuted; k rows permuted identically.
    uint32_t Bf[4][11][2];
    #pragma unroll
    for (int kk = 0; kk < 4; kk++) {
        const int kb = 16 * kk + 4 * q;
        #pragma unroll
        for (int nt = 0; nt < 11; nt++) {
            uint32_t b0, b1;
            if (nt < 8) {
                int pcol = 16 * (nt >> 1) + 4 * (tq >> 1) + 2 * (nt & 1) + (tq & 1);
                b0 = pack_h2(__float2half_rn(P[(kb    ) * DD + pcol]),
                             __float2half_rn(P[(kb + 1) * DD + pcol]));
                b1 = pack_h2(__float2half_rn(P[(kb + 2) * DD + pcol]),
                             __float2half_rn(P[(kb + 3) * DD + pcol]));
            } else {
                int n = 8 * nt + tq;
                if (n < DD + 2 * CC) {
                    int c = (n - DD) >> 1;
                    bool lo = (n - DD) & 1;
                    const float* mp = sMuP + c * DD;
                    b0 = pack_h2(muphalf(mp[kb], lo),     muphalf(mp[kb + 1], lo));
                    b1 = pack_h2(muphalf(mp[kb + 2], lo), muphalf(mp[kb + 3], lo));
                } else { b0 = 0u; b1 = 0u; }
            }
            Bf[kk][nt][0] = b0;
            Bf[kk][nt][1] = b1;
        }
    }

    const float alpha0 = __ldg(alpha_p);
    const float nq0 = sNegQ[q];
    const float nq1 = sNegQ[4 + q];
    const float nq2 = (q < 2) ? sNegQ[8 + q] : -CUDART_INF_F;

    const int idx0 = tq * 16 + q;          // float4 index: row tq,   chunk q (+4kk)
    const int idx1 = (tq + 8) * 16 + q;    //               row tq+8

    const int gw = blockIdx.x * 4 + w;
    const int stride = gridDim.x * 4;

    float4 raw[8];
    uint32_t Ah[4][4], Al[4][4];

    // prologue: load + convert first tile
    if (gw < nTiles16) {
        const float4* b4 = reinterpret_cast<const float4*>(F) + (size_t)gw * 256;
        #pragma unroll
        for (int kk = 0; kk < 4; kk++) {
            raw[2 * kk]     = __ldcs(b4 + idx0 + 4 * kk);
            raw[2 * kk + 1] = __ldcs(b4 + idx1 + 4 * kk);
        }
        #pragma unroll
        for (int kk = 0; kk < 4; kk++) {
            float4 v0 = raw[2 * kk], v1 = raw[2 * kk + 1];
            split2(v0.x, v0.y, Ah[kk][0], Al[kk][0]);
            split2(v1.x, v1.y, Ah[kk][1], Al[kk][1]);
            split2(v0.z, v0.w, Ah[kk][2], Al[kk][2]);
            split2(v1.z, v1.w, Ah[kk][3], Al[kk][3]);
        }
    }

    for (int tile = gw; tile < nTiles16; tile += stride) {
        // ---- prefetch next tile (latency hidden behind MMAs + epilogue) ----
        {
            int tn = tile + stride;
            if (tn >= nTiles16) tn = tile;
            const float4* bn = reinterpret_cast<const float4*>(F) + (size_t)tn * 256;
            #pragma unroll
            for (int kk = 0; kk < 4; kk++) {
                raw[2 * kk]     = __ldcs(bn + idx0 + 4 * kk);
                raw[2 * kk + 1] = __ldcs(bn + idx1 + 4 * kk);
            }
        }

        // ---- 44 MMAs on current frags (11 independent acc chains) ----
        float acc[11][4];
        #pragma unroll
        for (int nt = 0; nt < 11; nt++) {
            acc[nt][0] = 0.f; acc[nt][1] = 0.f; acc[nt][2] = 0.f; acc[nt][3] = 0.f;
        }
        #pragma unroll
        for (int kk = 0; kk < 4; kk++) {
            #pragma unroll
            for (int nt = 0; nt < 11; nt++) mma16816(acc[nt], Ah[kk], Bf[kk][nt]);
        }

        // ---- epilogue: qf = sum (fh + 2 fl)[sigma(n')] * D[m,n'] ----
        float qf0 = 0.f, qf1 = 0.f;
        #pragma unroll
        for (int nt = 0; nt < 8; nt++) {
            int kk = nt >> 1;
            int i0 = (nt & 1) ? 2 : 0;
            float2 h0 = h2f(Ah[kk][i0]),     l0 = h2f(Al[kk][i0]);       // row tq
            float2 h1 = h2f(Ah[kk][i0 + 1]), l1 = h2f(Al[kk][i0 + 1]);   // row tq+8
            qf0 = fmaf(fmaf(2.f, l0.x, h0.x), acc[nt][0], qf0);
            qf0 = fmaf(fmaf(2.f, l0.y, h0.y), acc[nt][1], qf0);
            qf1 = fmaf(fmaf(2.f, l1.x, h1.x), acc[nt][2], qf1);
            qf1 = fmaf(fmaf(2.f, l1.y, h1.y), acc[nt][3], qf1);
        }
        // class scores: thread q holds class q (nt8), 4+q (nt9), 8+q (nt10, q<2)
        float s0 = acc[8][0] + acc[8][1] + nq0;
        float s1 = acc[8][2] + acc[8][3] + nq0;
        s0 = fmaxf(s0, acc[9][0] + acc[9][1] + nq1);
        s1 = fmaxf(s1, acc[9][2] + acc[9][3] + nq1);
        s0 = fmaxf(s0, acc[10][0] + acc[10][1] + nq2);
        s1 = fmaxf(s1, acc[10][2] + acc[10][3] + nq2);

        #pragma unroll
        for (int o = 1; o <= 2; o <<= 1) {
            qf0 += __shfl_xor_sync(0xffffffffu, qf0, o);
            qf1 += __shfl_xor_sync(0xffffffffu, qf1, o);
            s0 = fmaxf(s0, __shfl_xor_sync(0xffffffffu, s0, o));
            s1 = fmaxf(s1, __shfl_xor_sync(0xffffffffu, s1, o));
        }
        if (q == 0) {
            float* o = out + (size_t)tile * 16;
            o[tq]     = alpha0 * (s0 - 0.5f * qf0);
            o[tq + 8] = alpha0 * (s1 - 0.5f * qf1);
        }

        // ---- convert prefetched raw -> frags for next iteration ----
        #pragma unroll
        for (int kk = 0; kk < 4; kk++) {
            float4 v0 = raw[2 * kk], v1 = raw[2 * kk + 1];
            split2(v0.x, v0.y, Ah[kk][0], Al[kk][0]);
            split2(v1.x, v1.y, Ah[kk][1], Al[kk][1]);
            split2(v0.z, v0.w, Ah[kk][2], Al[kk][2]);
            split2(v1.z, v1.w, Ah[kk][3], Al[kk][3]);
        }
    }
}

extern "C" void kernel_launch(void* const* d_in, const int* in_sizes, int n_in,
                              void* d_out, int out_size) {
    const float* features = (const float*)d_in[0];
    const float* mu       = (const float*)d_in[1];
    const float* P        = (const float*)d_in[2];
    const float* alpha    = (const float*)d_in[3];
    float* out = (float*)d_out;

    int n = in_sizes[0] / DD;
    int nTiles16 = n / 16;

    mahal_v10<<<296, 128>>>(features, mu, P, alpha, out, nTiles16);
}

// round 12
// speedup vs baseline: 1.6526x; 1.0724x over previous
#include <cuda_runtime.h>
#include <cuda_fp16.h>
#include <cstdint>
#include <math_constants.h>

// Mahalanobis max-score: all-register HMMA compute (validated R10 layout) +
// cp.async 3-stage warp-private smem pipeline for deep memory-level parallelism.
// Per 16-row tile (one warp): D[16, 88] = Fhi @ B via mma.m16n8k16 (44 MMAs):
//   logical B cols 0..63: P (fp16), k-perm pi / n-perm sigma so a-frags are
//     direct float4 reads and qf pairing stays thread-local.
//   cols 64..83: hi/lo fp16 col pairs of muP (cross = fh . muP, exact split)
// qf = sum_k (fh + 2 fl)[k] * D[m,k]
// out[m] = alpha * (max_c (Dh+Dl - 0.5 qmu_c) - 0.5 * qf)

#define DD 64
#define CC 10

static __device__ __forceinline__ uint32_t smem_u32(const void* p) {
    uint32_t a;
    asm("{ .reg .u64 t; cvta.to.shared.u64 t, %1; cvt.u32.u64 %0, t; }" : "=r"(a) : "l"(p));
    return a;
}
static __device__ __forceinline__ void cp_async16(uint32_t dst, const void* src) {
    asm volatile("cp.async.cg.shared.global [%0], [%1], 16;" :: "r"(dst), "l"(src) : "memory");
}
static __device__ __forceinline__ void cp_commit() {
    asm volatile("cp.async.commit_group;" ::: "memory");
}
static __device__ __forceinline__ void cp_wait1() {
    asm volatile("cp.async.wait_group 1;" ::: "memory");
}
static __device__ __forceinline__ float4 lds128(uint32_t addr) {
    float4 v;
    asm volatile("ld.shared.v4.f32 {%0,%1,%2,%3}, [%4];"
                 : "=f"(v.x), "=f"(v.y), "=f"(v.z), "=f"(v.w) : "r"(addr));
    return v;
}
static __device__ __forceinline__ void mma16816(float* d, const uint32_t* a, const uint32_t* b) {
    asm volatile(
        "mma.sync.aligned.m16n8k16.row.col.f32.f16.f16.f32 "
        "{%0,%1,%2,%3}, {%4,%5,%6,%7}, {%8,%9}, {%0,%1,%2,%3};"
        : "+f"(d[0]), "+f"(d[1]), "+f"(d[2]), "+f"(d[3])
        : "r"(a[0]), "r"(a[1]), "r"(a[2]), "r"(a[3]), "r"(b[0]), "r"(b[1]));
}
static __device__ __forceinline__ uint32_t pack_h2(__half a, __half b) {
    union { __half2 h; uint32_t u; } cv; cv.h = __halves2half2(a, b); return cv.u;
}
static __device__ __forceinline__ float2 h2f(uint32_t u) {
    union { uint32_t u; __half2 h; } cv; cv.u = u; return __half22float2(cv.h);
}
static __device__ __forceinline__ void split2(float x, float y, uint32_t& h, uint32_t& l) {
    __half2 hh = __float22half2_rn(make_float2(x, y));
    float2 hf = __half22float2(hh);
    __half2 ll = __float22half2_rn(make_float2(x - hf.x, y - hf.y));
    union { __half2 h; uint32_t u; } a, b;
    a.h = hh; b.h = ll;
    h = a.u; l = b.u;
}
static __device__ __forceinline__ __half muphalf(float v, bool lo) {
    __half h = __float2half_rn(v);
    return lo ? __float2half_rn(v - __half2float(h)) : h;
}
// stage layout: [16 rows][16 chunks of 16B]; chunk' = c ^ ((row & 3) << 2)
static __device__ __forceinline__ uint32_t st_off(int row, int c) {
    return (uint32_t)(row * 256 + ((c ^ ((row & 3) << 2)) << 4));
}

__global__ __launch_bounds__(128, 2)
void mahal_v12(const float* __restrict__ F, const float* __restrict__ mu,
               const float* __restrict__ P, const float* __restrict__ alpha_p,
               float* __restrict__ out, int nTiles16) {
    extern __shared__ __align__(16) uint8_t dynStage[];   // 4 warps x 3 stages x 4KB
    __shared__ float sMuP[CC * DD];
    __shared__ float sNegQ[16];

    const int tid = threadIdx.x;

    // ---- one-time prep: muP (fp32), -0.5*qmu ----
    for (int idx = tid; idx < CC * DD; idx += 128) {
        int c = idx >> 6, k = idx & 63;
        const float* mc = mu + c * DD;
        const float* pk = P + k * DD;        // P symmetric
        float s = 0.f;
        #pragma unroll 16
        for (int j = 0; j < DD; j++) s = fmaf(mc[j], pk[j], s);
        sMuP[idx] = s;
    }
    __syncthreads();
    if (tid < 16) {
        float v = 0.f;
        if (tid < CC) {
            float qq = 0.f;
            #pragma unroll 16
            for (int k = 0; k < DD; k++) qq = fmaf(sMuP[tid * DD + k], mu[tid * DD + k], qq);
            v = -0.5f * qq;
        }
        sNegQ[tid] = v;
    }
    __syncthreads();

    const int w  = tid >> 5;
    const int l  = tid & 31;
    const int q  = l & 3;
    const int tq = l >> 2;
    const uint32_t uStage = smem_u32(dynStage) + (uint32_t)w * 12288u;

    // ---- persistent B fragments, permuted layout (validated R10) ----
    uint32_t Bf[4][11][2];
    #pragma unroll
    for (int kk = 0; kk < 4; kk++) {
        const int kb = 16 * kk + 4 * q;
        #pragma unroll
        for (int nt = 0; nt < 11; nt++) {
            uint32_t b0, b1;
            if (nt < 8) {
                int pcol = 16 * (nt >> 1) + 4 * (tq >> 1) + 2 * (nt & 1) + (tq & 1);
                b0 = pack_h2(__float2half_rn(P[(kb    ) * DD + pcol]),
                             __float2half_rn(P[(kb + 1) * DD + pcol]));
                b1 = pack_h2(__float2half_rn(P[(kb + 2) * DD + pcol]),
                             __float2half_rn(P[(kb + 3) * DD + pcol]));
            } else {
                int n = 8 * nt + tq;
                if (n < DD + 2 * CC) {
                    int c = (n - DD) >> 1;
                    bool lo = (n - DD) & 1;
                    const float* mp = sMuP + c * DD;
                    b0 = pack_h2(muphalf(mp[kb], lo),     muphalf(mp[kb + 1], lo));
                    b1 = pack_h2(muphalf(mp[kb + 2], lo), muphalf(mp[kb + 3], lo));
                } else { b0 = 0u; b1 = 0u; }
            }
            Bf[kk][nt][0] = b0;
            Bf[kk][nt][1] = b1;
        }
    }

    const float alpha0 = __ldg(alpha_p);
    const float nq0 = sNegQ[q];
    const float nq1 = sNegQ[4 + q];
    const float nq2 = (q < 2) ? sNegQ[8 + q] : -CUDART_INF_F;

    const int gw = blockIdx.x * 4 + w;
    const int stride = gridDim.x * 4;
    const float4* Fb = reinterpret_cast<const float4*>(F);

    const int sc = l & 15;

    uint32_t Ah[4][4], Al[4][4];

    // issue one tile's 8 cp.asyncs into stage s (skips if t out of range)
    auto issue = [&](int t, int s) {
        if (t < nTiles16) {
            const float4* src = Fb + (size_t)t * 256;
            uint32_t dst = uStage + (uint32_t)s * 4096u;
            #pragma unroll
            for (int j = 0; j < 8; j++) {
                int row = 2 * j + (l >> 4);
                cp_async16(dst + st_off(row, sc), src + (j * 32 + l));
            }
        }
        cp_commit();
    };
    // convert stage s -> Ah/Al frags
    auto convert = [&](int s) {
        uint32_t base = uStage + (uint32_t)s * 4096u;
        #pragma unroll
        for (int kk = 0; kk < 4; kk++) {
            int c0 = q + 4 * kk;
            float4 v0 = lds128(base + st_off(tq, c0));
            float4 v1 = lds128(base + st_off(tq + 8, c0));
            split2(v0.x, v0.y, Ah[kk][0], Al[kk][0]);
            split2(v1.x, v1.y, Ah[kk][1], Al[kk][1]);
            split2(v0.z, v0.w, Ah[kk][2], Al[kk][2]);
            split2(v1.z, v1.w, Ah[kk][3], Al[kk][3]);
        }
    };

    // ---- prologue: fill stage0, convert; launch stage1 ----
    issue(gw, 0);
    asm volatile("cp.async.wait_group 0;" ::: "memory");
    __syncwarp();
    if (gw < nTiles16) convert(0);
    issue(gw + stride, 1);

    int si = 0;
    for (int tile = gw; tile < nTiles16; tile += stride) {
        // stage t+2 into (si+2)%3
        int s2 = si + 2; if (s2 >= 3) s2 -= 3;
        issue(tile + 2 * stride, s2);

        // ---- 44 MMAs on current frags ----
        float acc[11][4];
        #pragma unroll
        for (int nt = 0; nt < 11; nt++) {
            acc[nt][0] = 0.f; acc[nt][1] = 0.f; acc[nt][2] = 0.f; acc[nt][3] = 0.f;
        }
        #pragma unroll
        for (int kk = 0; kk < 4; kk++) {
            #pragma unroll
            for (int nt = 0; nt < 11; nt++) mma16816(acc[nt], Ah[kk], Bf[kk][nt]);
        }

        // ---- epilogue: qf = sum (fh + 2 fl) * D ----
        float qf0 = 0.f, qf1 = 0.f;
        #pragma unroll
        for (int nt = 0; nt < 8; nt++) {
            int kk = nt >> 1;
            int i0 = (nt & 1) ? 2 : 0;
            float2 h0 = h2f(Ah[kk][i0]),     l0 = h2f(Al[kk][i0]);       // row tq
            float2 h1 = h2f(Ah[kk][i0 + 1]), l1 = h2f(Al[kk][i0 + 1]);   // row tq+8
            qf0 = fmaf(fmaf(2.f, l0.x, h0.x), acc[nt][0], qf0);
            qf0 = fmaf(fmaf(2.f, l0.y, h0.y), acc[nt][1], qf0);
            qf1 = fmaf(fmaf(2.f, l1.x, h1.x), acc[nt][2], qf1);
            qf1 = fmaf(fmaf(2.f, l1.y, h1.y), acc[nt][3], qf1);
        }
        float s0 = acc[8][0] + acc[8][1] + nq0;
        float s1 = acc[8][2] + acc[8][3] + nq0;
        s0 = fmaxf(s0, acc[9][0] + acc[9][1] + nq1);
        s1 = fmaxf(s1, acc[9][2] + acc[9][3] + nq1);
        s0 = fmaxf(s0, acc[10][0] + acc[10][1] + nq2);
        s1 = fmaxf(s1, acc[10][2] + acc[10][3] + nq2);

        #pragma unroll
        for (int o = 1; o <= 2; o <<= 1) {
            qf0 += __shfl_xor_sync(0xffffffffu, qf0, o);
            qf1 += __shfl_xor_sync(0xffffffffu, qf1, o);
            s0 = fmaxf(s0, __shfl_xor_sync(0xffffffffu, s0, o));
            s1 = fmaxf(s1, __shfl_xor_sync(0xffffffffu, s1, o));
        }
        if (q == 0) {
            float* o = out + (size_t)tile * 16;
            o[tq]     = alpha0 * (s0 - 0.5f * qf0);
            o[tq + 8] = alpha0 * (s1 - 0.5f * qf1);
        }

        // ---- wait stage t+1, convert for next iteration ----
        cp_wait1();
        __syncwarp();
        int s1i = si + 1; if (s1i >= 3) s1i -= 3;
        if (tile + stride < nTiles16) convert(s1i);
        si = s1i;
    }
}

extern "C" void kernel_launch(void* const* d_in, const int* in_sizes, int n_in,
                              void* d_out, int out_size) {
    const float* features = (const float*)d_in[0];
    const float* mu       = (const float*)d_in[1];
    const float* P        = (const float*)d_in[2];
    const float* alpha    = (const float*)d_in[3];
    float* out = (float*)d_out;

    int n = in_sizes[0] / DD;
    int nTiles16 = n / 16;

    static bool attr_set = false;
    if (!attr_set) {
        cudaFuncSetAttribute(mahal_v12, cudaFuncAttributeMaxDynamicSharedMemorySize, 49152);
        attr_set = true;
    }

    mahal_v12<<<296, 128, 49152>>>(features, mu, P, alpha, out, nTiles16);
}